// round 8
// baseline (speedup 1.0000x reference)
#include <cuda_runtime.h>
#include <cuda_bf16.h>
#include <cstdint>
#include <math.h>

// Problem constants
#define NB   32
#define TLEN 512
#define DDIM 1024
#define CDIM 120
#define NROWS 96
#define INV_SCALE 0.015625f // 1/64
#define TOTROWS 49152

#define NEG_INF __int_as_float(0xff800000)

// ---------------- scratch (device globals) ----------------------------------
__device__ float g_xsum[NROWS * DDIM];
__device__ float g_nv[NROWS];
__device__ float g_u[NROWS * DDIM];
__device__ float g_ub[NROWS];
__device__ float g_v[NROWS * DDIM];
__device__ float g_s[NROWS * TLEN];
__device__ float g_ph[NROWS * DDIM];
__device__ float g_pooled[NROWS * DDIM];
__device__ int   g_rank[NROWS * TLEN];
__device__ int   g_V[NROWS];
// operands for the tensor-core GEMM (compacted rows)
// bf16 hi planes are pre-scaled by 2^7; fp8 planes: xh8=x*2^3, xl8=xl*2^8,
// wh8=w*2^6, wl8=wl*2^11  =>  every product carries scale 2^14.
__device__ __nv_bfloat16 g_xhi[(size_t)TOTROWS * DDIM];
__device__ __align__(16) unsigned char g_xh8[(size_t)TOTROWS * DDIM];
__device__ __align__(16) unsigned char g_xl8[(size_t)TOTROWS * DDIM];
__device__ __nv_bfloat16 g_w1t_hi[DDIM * DDIM];
__device__ __align__(16) unsigned char g_w1t_h8[DDIM * DDIM];
__device__ __align__(16) unsigned char g_w1t_l8[DDIM * DDIM];

// =================== helpers =================================================
__device__ __forceinline__ void cp16(void* d, const void* s) {
    asm volatile("cp.async.cg.shared.global [%0], [%1], 16;"
                 :: "l"(__cvta_generic_to_shared(d)), "l"(s));
}
__device__ __forceinline__ void cp_commit() {
    asm volatile("cp.async.commit_group;" ::: "memory");
}
__device__ __forceinline__ void cp_wait1() {
    asm volatile("cp.async.wait_group 1;" ::: "memory");
}
__device__ __forceinline__ void cp_wait0() {
    asm volatile("cp.async.wait_group 0;" ::: "memory");
}
__device__ __forceinline__ void mma_bf16(float* d, const uint32_t* a, const uint32_t* b) {
    asm volatile(
        "mma.sync.aligned.m16n8k16.row.col.f32.bf16.bf16.f32 "
        "{%0,%1,%2,%3}, {%4,%5,%6,%7}, {%8,%9}, {%0,%1,%2,%3};"
        : "+f"(d[0]), "+f"(d[1]), "+f"(d[2]), "+f"(d[3])
        : "r"(a[0]), "r"(a[1]), "r"(a[2]), "r"(a[3]), "r"(b[0]), "r"(b[1]));
}
__device__ __forceinline__ void mma_fp8(float* d, const uint32_t* a, const uint32_t* b) {
    asm volatile(
        "mma.sync.aligned.m16n8k32.row.col.f32.e4m3.e4m3.f32 "
        "{%0,%1,%2,%3}, {%4,%5,%6,%7}, {%8,%9}, {%0,%1,%2,%3};"
        : "+f"(d[0]), "+f"(d[1]), "+f"(d[2]), "+f"(d[3])
        : "r"(a[0]), "r"(a[1]), "r"(a[2]), "r"(a[3]), "r"(b[0]), "r"(b[1]));
}
__device__ __forceinline__ void ldm4(uint32_t* r, uint32_t saddr) {
    asm volatile("ldmatrix.sync.aligned.m8n8.x4.shared.b16 {%0,%1,%2,%3}, [%4];"
                 : "=r"(r[0]), "=r"(r[1]), "=r"(r[2]), "=r"(r[3]) : "r"(saddr));
}
__device__ __forceinline__ uint32_t pack4_e4m3(float f0, float f1, float f2, float f3) {
    uint16_t lo, hi;
    asm("cvt.rn.satfinite.e4m3x2.f32 %0, %1, %2;" : "=h"(lo) : "f"(f1), "f"(f0));
    asm("cvt.rn.satfinite.e4m3x2.f32 %0, %1, %2;" : "=h"(hi) : "f"(f3), "f"(f2));
    return ((uint32_t)hi << 16) | (uint32_t)lo;
}

// SMEM stage layout (per stage, K=32):
//  ABH  bf16 A-hi 128x(64B data,80B stride) = 10240
//  BBH  bf16 B-hi                          = 10240
//  AH8/AL8/BH8/BL8 fp8 128x(32B data,48B stride) = 6144 each
#define ROW_BF    80
#define ROW_F8    48
#define OFF_BBH   10240
#define OFF_AH8   20480
#define OFF_AL8   26624
#define OFF_BH8   32768
#define OFF_BL8   38912
#define STAGE_B   45056
#define OFF_SEXP  90112
#define OFF_B1    92160
#define OFF_COL   92672
#define OFF_RED   93184
#define SMEM_REQ  94208
#define INV16K    6.103515625e-05f

// ---------------- K0: zero scratch + conv W1 (fused) ------------------------
__global__ void combo_kernel(const float* __restrict__ W1,
                             __nv_bfloat16* __restrict__ th,
                             unsigned char* __restrict__ wh8,
                             unsigned char* __restrict__ wl8,
                             float* __restrict__ ph, float* __restrict__ xsum,
                             float* __restrict__ u, float* __restrict__ v,
                             float* __restrict__ pooled, float* __restrict__ ub) {
    int bx = blockIdx.x;
    if (bx < 384) {
        int i = bx * 256 + threadIdx.x;
        ph[i] = 0.f; xsum[i] = 0.f; u[i] = 0.f; v[i] = 0.f; pooled[i] = 0.f;
        if (i < NROWS) ub[i] = 0.f;
    } else {
        __shared__ float tile[32][33];
        int b = bx - 384;
        int n0 = (b & 31) * 32, k0 = (b >> 5) * 32;
        int tx = threadIdx.x & 31, ty = threadIdx.x >> 5;
        for (int r = ty; r < 32; r += 8)
            tile[r][tx] = W1[(size_t)(k0 + r) * DDIM + n0 + tx];
        __syncthreads();
        for (int r = ty; r < 32; r += 8) {
            float w = tile[tx][r];  // = W1[k0+tx][n0+r]
            __nv_bfloat16 h = __float2bfloat16(w);
            float hf = __bfloat162float(h);
            float l = w - hf;
            size_t o = (size_t)(n0 + r) * DDIM + k0 + tx;
            th[o] = __float2bfloat16(hf * 128.f);  // exact (exponent shift)
            uint16_t p8;
            asm("cvt.rn.satfinite.e4m3x2.f32 %0, %1, %2;"
                : "=h"(p8) : "f"(0.f), "f"(w * 64.f));
            wh8[o] = (unsigned char)(p8 & 0xff);
            asm("cvt.rn.satfinite.e4m3x2.f32 %0, %1, %2;"
                : "=h"(p8) : "f"(0.f), "f"(l * 2048.f));
            wl8[o] = (unsigned char)(p8 & 0xff);
        }
    }
}

// ---------------- K0b: mask scan -> rank/V/nv --------------------------------
__global__ void mask_scan_kernel(const int* __restrict__ m0, const int* __restrict__ m1,
                                 const int* __restrict__ m2,
                                 int* __restrict__ rank, int* __restrict__ V,
                                 float* __restrict__ nv) {
    int b = blockIdx.x, br = blockIdx.y;
    const int* M = ((br == 0) ? m0 : (br == 1) ? m1 : m2) + (size_t)b * TLEN;
    int row = br * NB + b;
    int tid = threadIdx.x;  // 512
    __shared__ int ps[TLEN];
    int valid = (M[tid] == 0) ? 1 : 0;
    ps[tid] = valid;
    __syncthreads();
    for (int off = 1; off < TLEN; off <<= 1) {
        int vv = (tid >= off) ? ps[tid - off] : 0;
        __syncthreads();
        ps[tid] += vv;
        __syncthreads();
    }
    rank[row * TLEN + tid] = valid ? (ps[tid] - 1) : -1;
    if (tid == TLEN - 1) {
        V[row] = ps[TLEN - 1];
        nv[row] = (float)ps[TLEN - 1];
    }
}

// ---------------- fused: valid x -> compacted bf16/fp8 planes + masked sum --
__global__ void convsum_kernel(const float* __restrict__ x0, const float* __restrict__ x1,
                               const float* __restrict__ x2,
                               const int* __restrict__ rank,
                               __nv_bfloat16* __restrict__ xhi,
                               unsigned char* __restrict__ xh8,
                               unsigned char* __restrict__ xl8,
                               float* __restrict__ xsum) {
    int ch = blockIdx.x, b = blockIdx.y, br = blockIdx.z;
    const float* X = (br == 0) ? x0 : (br == 1) ? x1 : x2;
    int row = br * NB + b;
    __shared__ int smr[64];
    int tid = threadIdx.x;
    if (tid < 64) smr[tid] = rank[row * TLEN + ch * 64 + tid];
    __syncthreads();

    const float* xp = X + ((size_t)b * TLEN + ch * 64) * DDIM + tid * 4;
    size_t cbase = (size_t)row * TLEN;
    float ax = 0.f, ay = 0.f, az = 0.f, aw = 0.f;
    for (int t = 0; t < 64; t++) {
        int rk = smr[t];
        if (rk >= 0) {
            float4 v = *(const float4*)(xp + (size_t)t * DDIM);
            __nv_bfloat16 h0 = __float2bfloat16(v.x);
            __nv_bfloat16 h1 = __float2bfloat16(v.y);
            __nv_bfloat16 h2 = __float2bfloat16(v.z);
            __nv_bfloat16 h3 = __float2bfloat16(v.w);
            float hf0 = __bfloat162float(h0), hf1 = __bfloat162float(h1);
            float hf2 = __bfloat162float(h2), hf3 = __bfloat162float(h3);
            size_t o = (cbase + rk) * DDIM + tid * 4;
            __nv_bfloat162* ph2 = (__nv_bfloat162*)(xhi + o);
            ph2[0] = __nv_bfloat162(__float2bfloat16(hf0 * 128.f),
                                    __float2bfloat16(hf1 * 128.f));
            ph2[1] = __nv_bfloat162(__float2bfloat16(hf2 * 128.f),
                                    __float2bfloat16(hf3 * 128.f));
            *(uint32_t*)(xh8 + o) =
                pack4_e4m3(v.x * 8.f, v.y * 8.f, v.z * 8.f, v.w * 8.f);
            *(uint32_t*)(xl8 + o) =
                pack4_e4m3((v.x - hf0) * 256.f, (v.y - hf1) * 256.f,
                           (v.z - hf2) * 256.f, (v.w - hf3) * 256.f);
            ax += v.x; ay += v.y; az += v.z; aw += v.w;
        }
    }
    float* xr = xsum + (size_t)row * DDIM + tid * 4;
    atomicAdd(xr + 0, ax);
    atomicAdd(xr + 1, ay);
    atomicAdd(xr + 2, az);
    atomicAdd(xr + 3, aw);
}

// ---------------- small GEMM, K-split x4 -------------------------------------
template <int MODE>
__global__ void gemm96_kernel(const float* __restrict__ A, const float* __restrict__ B,
                              float* __restrict__ C, const float* __restrict__ bias,
                              const float* __restrict__ nv, float* __restrict__ ub) {
    const int BK = 32;
    __shared__ float As[32][BK + 1];
    __shared__ float Bs[BK][64 + 1];
    int m0 = blockIdx.y * 32;
    int n0 = blockIdx.x * 64;
    int ks = blockIdx.z * 256;
    int tid = threadIdx.x;
    int tx = tid & 15, ty = tid >> 4;
    int lane = tid & 31;

    float acc[2][4] = {{0.f, 0.f, 0.f, 0.f}, {0.f, 0.f, 0.f, 0.f}};

    for (int k0 = ks; k0 < ks + 256; k0 += BK) {
#pragma unroll
        for (int i = 0; i < 4; i++) {
            int l = tid + i * 256;
            int r = l >> 5, k = l & 31;
            As[r][k] = A[(size_t)(m0 + r) * DDIM + k0 + k];
        }
        if (MODE == 1) {
#pragma unroll
            for (int i = 0; i < 8; i++) {
                int l = tid + i * 256;
                int kk = l & 31, n = l >> 5;
                Bs[kk][n] = B[(size_t)(n0 + n) * DDIM + k0 + kk];
            }
        } else {
#pragma unroll
            for (int i = 0; i < 8; i++) {
                int l = tid + i * 256;
                int kk = l >> 6, n = l & 63;
                Bs[kk][n] = B[(size_t)(k0 + kk) * DDIM + n0 + n];
            }
        }
        __syncthreads();
#pragma unroll
        for (int kk = 0; kk < BK; kk++) {
            float a0 = As[ty * 2 + 0][kk];
            float a1 = As[ty * 2 + 1][kk];
#pragma unroll
            for (int j = 0; j < 4; j++) {
                float bv = Bs[kk][tx * 4 + j];
                acc[0][j] += a0 * bv;
                acc[1][j] += a1 * bv;
            }
        }
        __syncthreads();
    }

    float vv[2][4];
#pragma unroll
    for (int i = 0; i < 2; i++) {
        int r = m0 + ty * 2 + i;
#pragma unroll
        for (int j = 0; j < 4; j++) {
            int c = n0 + tx * 4 + j;
            float v = acc[i][j];
            if (MODE == 0 && blockIdx.z == 0) v += nv[r] * bias[c];
            if (MODE == 2 && blockIdx.z == 0) v += bias[c];
            vv[i][j] = v;
            atomicAdd(&C[(size_t)r * DDIM + c], v);
        }
    }
    if (MODE == 0) {
        float u0 = 0.f, u1 = 0.f;
#pragma unroll
        for (int j = 0; j < 4; j++) {
            float ba = bias[n0 + tx * 4 + j];
            u0 += vv[0][j] * ba;
            u1 += vv[1][j] * ba;
        }
#pragma unroll
        for (int o = 8; o > 0; o >>= 1) {
            u0 += __shfl_xor_sync(0xffffffffu, u0, o);
            u1 += __shfl_xor_sync(0xffffffffu, u1, o);
        }
        if ((lane & 15) == 0) {
            atomicAdd(&ub[m0 + ty * 2 + 0], u0);
            atomicAdd(&ub[m0 + ty * 2 + 1], u1);
        }
    }
}

// ---------------- K3: compacted s[row][rank] ---------------------------------
__global__ void s_kernel(const float* __restrict__ x0, const float* __restrict__ x1,
                         const float* __restrict__ x2,
                         const int* __restrict__ rank,
                         const float* __restrict__ v, const float* __restrict__ ub,
                         float* __restrict__ s) {
    int br = blockIdx.z, b = blockIdx.y;
    int w = threadIdx.x >> 5, lane = threadIdx.x & 31;
    int t = blockIdx.x * 8 + w;
    const float* X = (br == 0) ? x0 : (br == 1) ? x1 : x2;
    int row = br * NB + b;
    int rk = rank[row * TLEN + t];
    if (rk < 0) return;
    const float* xr = X + ((size_t)b * TLEN + t) * DDIM;
    const float* vr = v + (size_t)row * DDIM;
    float acc = 0.f;
#pragma unroll
    for (int i = 0; i < 8; i++) {
        int d = lane * 4 + i * 128;
        float4 xv = *(const float4*)&xr[d];
        float4 vv = *(const float4*)&vr[d];
        acc += xv.x * vv.x + xv.y * vv.y + xv.z * vv.z + xv.w * vv.w;
    }
#pragma unroll
    for (int o = 16; o > 0; o >>= 1) acc += __shfl_xor_sync(0xffffffffu, acc, o);
    if (lane == 0) s[row * TLEN + rk] = (acc + ub[row]) * INV_SCALE;
}

// ---------------- K5: bf16-hh + fp8-cross mma GEMM over compacted rows ------
// grid (8, 384): bx = N-block (128 cols); arow = by>>2, tile = by&3.
__global__ __launch_bounds__(256, 2) void big_mma_kernel(
    const __nv_bfloat16* __restrict__ xhi,
    const unsigned char* __restrict__ xh8, const unsigned char* __restrict__ xl8,
    const __nv_bfloat16* __restrict__ wthi,
    const unsigned char* __restrict__ wh8, const unsigned char* __restrict__ wl8,
    const float* __restrict__ b1, const float* __restrict__ s,
    const int* __restrict__ Varr, float* __restrict__ ph) {
    extern __shared__ __align__(16) char smc[];
    float* sexp = (float*)(smc + OFF_SEXP);
    float* b1s  = (float*)(smc + OFF_B1);
    float* cols = (float*)(smc + OFF_COL);
    float* sred = (float*)(smc + OFF_RED);
    uint32_t sbase = (uint32_t)__cvta_generic_to_shared(smc);

    int by = blockIdx.y;
    int arow = by >> 2, tile = by & 3;
    int V = Varr[arow];
    if (tile * 128 >= V) return;

    int tid = threadIdx.x;
    int wid = tid >> 5, lane = tid & 31;
    int wm = wid >> 2, wn = wid & 3;
    int g = lane >> 2, tg = lane & 3;
    int n0 = blockIdx.x * 128;
    size_t rowbase = (size_t)arow * TLEN + tile * 128;

    auto load_stage = [&](int st) {
        char* buf = smc + (st & 1) * STAGE_B;
        int k0 = st * 32;
#pragma unroll
        for (int c = tid; c < 512; c += 256) {
            int r = c >> 2, j = c & 3;
            cp16(buf + r * ROW_BF + j * 16, xhi + (rowbase + r) * DDIM + k0 + j * 8);
            cp16(buf + OFF_BBH + r * ROW_BF + j * 16,
                 wthi + (size_t)(n0 + r) * DDIM + k0 + j * 8);
        }
        {
            int r = tid >> 1, j = tid & 1;
            size_t ao = (rowbase + r) * DDIM + k0 + j * 16;
            size_t bo = (size_t)(n0 + r) * DDIM + k0 + j * 16;
            int off = r * ROW_F8 + j * 16;
            cp16(buf + OFF_AH8 + off, xh8 + ao);
            cp16(buf + OFF_AL8 + off, xl8 + ao);
            cp16(buf + OFF_BH8 + off, wh8 + bo);
            cp16(buf + OFF_BL8 + off, wl8 + bo);
        }
    };

    load_stage(0); cp_commit();

    // ---- fused softmax over compact s (length V) ----
    {
        float v0 = (tid < V) ? s[arow * TLEN + tid] : NEG_INF;
        float v1 = (tid + 256 < V) ? s[arow * TLEN + tid + 256] : NEG_INF;
        sred[tid] = fmaxf(v0, v1);
        __syncthreads();
        for (int st = 128; st > 0; st >>= 1) {
            if (tid < st) sred[tid] = fmaxf(sred[tid], sred[tid + st]);
            __syncthreads();
        }
        float mx = sred[0];
        __syncthreads();
        float e0 = (tid < V) ? expf(v0 - mx) : 0.f;
        float e1 = (tid + 256 < V) ? expf(v1 - mx) : 0.f;
        sred[tid] = e0 + e1;
        __syncthreads();
        for (int st = 128; st > 0; st >>= 1) {
            if (tid < st) sred[tid] += sred[tid + st];
            __syncthreads();
        }
        float inv = 1.0f / sred[0];
        sexp[tid] = e0 * inv;
        sexp[tid + 256] = e1 * inv;
    }
    if (tid < 128) { b1s[tid] = b1[n0 + tid]; cols[tid] = 0.f; }

    float acc[4][4][4];
#pragma unroll
    for (int mi = 0; mi < 4; mi++)
#pragma unroll
        for (int ni = 0; ni < 4; ni++)
#pragma unroll
            for (int j = 0; j < 4; j++) acc[mi][ni][j] = 0.f;

    uint32_t a_l = (uint32_t)((wm * 64 + (lane & 15)) * ROW_BF + (lane >> 4) * 16);
    uint32_t b_l = (uint32_t)((wn * 32 + (lane & 7) + ((lane >> 4) << 3)) * ROW_BF +
                              ((lane >> 3) & 1) * 16);
    uint32_t a8_l = (uint32_t)((wm * 64 + (lane & 15)) * ROW_F8 + (lane >> 4) * 16);
    uint32_t b8_l = (uint32_t)((wn * 32 + (lane & 7) + ((lane >> 4) << 3)) * ROW_F8 +
                               ((lane >> 3) & 1) * 16);

    for (int st = 0; st < 32; ++st) {
        if (st + 1 < 32) { load_stage(st + 1); cp_commit(); cp_wait1(); }
        else            { cp_wait0(); }
        __syncthreads();
        uint32_t buf = sbase + (uint32_t)(st & 1) * STAGE_B;
        // ---- bf16 hi*hi (scale 2^14) ----
#pragma unroll
        for (int ksub = 0; ksub < 2; ++ksub) {
            uint32_t aoff = buf + a_l + (uint32_t)ksub * 32u;
            uint32_t boff = buf + OFF_BBH + b_l + (uint32_t)ksub * 32u;
            uint32_t a[4][4], bh[2][4];
#pragma unroll
            for (int mi = 0; mi < 4; mi++) ldm4(a[mi], aoff + mi * (16 * ROW_BF));
#pragma unroll
            for (int p = 0; p < 2; p++) ldm4(bh[p], boff + p * (16 * ROW_BF));
#pragma unroll
            for (int mi = 0; mi < 4; mi++)
#pragma unroll
                for (int ni = 0; ni < 4; ni++)
                    mma_bf16(acc[mi][ni], a[mi], &bh[ni >> 1][(ni & 1) * 2]);
        }
        // ---- fp8 cross terms (scale 2^14), K=32 per MMA ----
        {
            uint32_t a8[4][4], b8[2][4];
#pragma unroll
            for (int mi = 0; mi < 4; mi++)
                ldm4(a8[mi], buf + OFF_AH8 + a8_l + mi * (16 * ROW_F8));
#pragma unroll
            for (int p = 0; p < 2; p++)
                ldm4(b8[p], buf + OFF_BL8 + b8_l + p * (16 * ROW_F8));
#pragma unroll
            for (int mi = 0; mi < 4; mi++)
#pragma unroll
                for (int ni = 0; ni < 4; ni++)
                    mma_fp8(acc[mi][ni], a8[mi], &b8[ni >> 1][(ni & 1) * 2]);
#pragma unroll
            for (int mi = 0; mi < 4; mi++)
                ldm4(a8[mi], buf + OFF_AL8 + a8_l + mi * (16 * ROW_F8));
#pragma unroll
            for (int p = 0; p < 2; p++)
                ldm4(b8[p], buf + OFF_BH8 + b8_l + p * (16 * ROW_F8));
#pragma unroll
            for (int mi = 0; mi < 4; mi++)
#pragma unroll
                for (int ni = 0; ni < 4; ni++)
                    mma_fp8(acc[mi][ni], a8[mi], &b8[ni >> 1][(ni & 1) * 2]);
        }
        __syncthreads();
    }

    // ---- epilogue: pooled_col += sum_rows attn[row]*relu(acc*2^-14 + b1) ----
    const float* att_s = sexp + tile * 128;
#pragma unroll
    for (int mi = 0; mi < 4; mi++) {
        int rA = wm * 64 + mi * 16 + g;
        float wA = att_s[rA], wB = att_s[rA + 8];
#pragma unroll
        for (int ni = 0; ni < 4; ni++) {
            int c0 = wn * 32 + ni * 8 + tg * 2;
            float bv0 = b1s[c0], bv1 = b1s[c0 + 1];
            float v0 = fmaxf(acc[mi][ni][0] * INV16K + bv0, 0.f) * wA +
                       fmaxf(acc[mi][ni][2] * INV16K + bv0, 0.f) * wB;
            float v1 = fmaxf(acc[mi][ni][1] * INV16K + bv1, 0.f) * wA +
                       fmaxf(acc[mi][ni][3] * INV16K + bv1, 0.f) * wB;
#pragma unroll
            for (int o = 4; o <= 16; o <<= 1) {
                v0 += __shfl_xor_sync(0xffffffffu, v0, o);
                v1 += __shfl_xor_sync(0xffffffffu, v1, o);
            }
            if (g == 0) {
                atomicAdd(&cols[c0], v0);
                atomicAdd(&cols[c0 + 1], v1);
            }
        }
    }
    __syncthreads();
    if (tid < 128) atomicAdd(&ph[(size_t)arow * DDIM + n0 + tid], cols[tid]);
}

// ---------------- K6: layernorm + relu + last linear -----------------------
__global__ void final_kernel(const float* __restrict__ pooled,
                             const float* __restrict__ ln_g, const float* __restrict__ ln_b,
                             const float* __restrict__ W_last, const float* __restrict__ b_last,
                             float* __restrict__ out) {
    int row = blockIdx.y * NB + blockIdx.x;
    int tid = threadIdx.x;
    __shared__ float act[DDIM];
    __shared__ float red[128];

    float vals[8];
    float lsum = 0.f;
#pragma unroll
    for (int i = 0; i < 8; i++) {
        vals[i] = pooled[(size_t)row * DDIM + tid + i * 128];
        lsum += vals[i];
    }
    red[tid] = lsum;
    __syncthreads();
    for (int s = 64; s > 0; s >>= 1) {
        if (tid < s) red[tid] += red[tid + s];
        __syncthreads();
    }
    float mu = red[0] * (1.0f / DDIM);
    __syncthreads();
    float lsq = 0.f;
#pragma unroll
    for (int i = 0; i < 8; i++) {
        float d = vals[i] - mu;
        lsq += d * d;
    }
    red[tid] = lsq;
    __syncthreads();
    for (int s = 64; s > 0; s >>= 1) {
        if (tid < s) red[tid] += red[tid + s];
        __syncthreads();
    }
    float var = red[0] * (1.0f / DDIM);
    float vv = var + 1e-12f;
    float inv = rsqrtf(vv);
    inv = inv * (1.5f - 0.5f * vv * inv * inv);
    __syncthreads();
#pragma unroll
    for (int i = 0; i < 8; i++) {
        int d = tid + i * 128;
        float nvv = (vals[i] - mu) * inv * ln_g[d] + ln_b[d];
        act[d] = fmaxf(nvv, 0.f);
    }
    __syncthreads();
    if (tid < CDIM) {
        float accv = b_last[tid];
        for (int d = 0; d < DDIM; d++) accv += act[d] * W_last[(size_t)d * CDIM + tid];
        out[(size_t)row * CDIM + tid] = accv;
    }
}

// ---------------- launch ----------------------------------------------------
extern "C" void kernel_launch(void* const* d_in, const int* in_sizes, int n_in,
                              void* d_out, int out_size) {
    const float* x0 = (const float*)d_in[0];
    const float* x1 = (const float*)d_in[1];
    const float* x2 = (const float*)d_in[2];
    const int* m0 = (const int*)d_in[3];
    const int* m1 = (const int*)d_in[4];
    const int* m2 = (const int*)d_in[5];
    const float* W_attn = (const float*)d_in[6];
    const float* b_attn = (const float*)d_in[7];
    const float* W1 = (const float*)d_in[8];
    const float* b1 = (const float*)d_in[9];
    const float* W2 = (const float*)d_in[10];
    const float* b2 = (const float*)d_in[11];
    const float* ln_g = (const float*)d_in[12];
    const float* ln_b = (const float*)d_in[13];
    const float* W_last = (const float*)d_in[14];
    const float* b_last = (const float*)d_in[15];
    float* out = (float*)d_out;

    float *p_xsum, *p_nv, *p_u, *p_ub, *p_v, *p_s, *p_ph, *p_pooled;
    int *p_rank, *p_V;
    __nv_bfloat16 *p_xhi, *p_wthi;
    unsigned char *p_xh8, *p_xl8, *p_wh8, *p_wl8;
    cudaGetSymbolAddress((void**)&p_xsum, g_xsum);
    cudaGetSymbolAddress((void**)&p_nv, g_nv);
    cudaGetSymbolAddress((void**)&p_u, g_u);
    cudaGetSymbolAddress((void**)&p_ub, g_ub);
    cudaGetSymbolAddress((void**)&p_v, g_v);
    cudaGetSymbolAddress((void**)&p_s, g_s);
    cudaGetSymbolAddress((void**)&p_ph, g_ph);
    cudaGetSymbolAddress((void**)&p_pooled, g_pooled);
    cudaGetSymbolAddress((void**)&p_rank, g_rank);
    cudaGetSymbolAddress((void**)&p_V, g_V);
    cudaGetSymbolAddress((void**)&p_xhi, g_xhi);
    cudaGetSymbolAddress((void**)&p_xh8, g_xh8);
    cudaGetSymbolAddress((void**)&p_xl8, g_xl8);
    cudaGetSymbolAddress((void**)&p_wthi, g_w1t_hi);
    cudaGetSymbolAddress((void**)&p_wh8, g_w1t_h8);
    cudaGetSymbolAddress((void**)&p_wl8, g_w1t_l8);

    cudaFuncSetAttribute(big_mma_kernel, cudaFuncAttributeMaxDynamicSharedMemorySize,
                         SMEM_REQ);

    combo_kernel<<<1408, 256>>>(W1, p_wthi, p_wh8, p_wl8, p_ph, p_xsum, p_u, p_v,
                                p_pooled, p_ub);
    mask_scan_kernel<<<dim3(NB, 3), 512>>>(m0, m1, m2, p_rank, p_V, p_nv);
    convsum_kernel<<<dim3(8, NB, 3), 256>>>(x0, x1, x2, p_rank,
                                            p_xhi, p_xh8, p_xl8, p_xsum);
    gemm96_kernel<0><<<dim3(16, 3, 4), 256>>>(p_xsum, W_attn, p_u, b_attn, p_nv, p_ub);
    gemm96_kernel<1><<<dim3(16, 3, 4), 256>>>(p_u, W_attn, p_v, nullptr, nullptr, nullptr);
    s_kernel<<<dim3(64, NB, 3), 256>>>(x0, x1, x2, p_rank, p_v, p_ub, p_s);
    big_mma_kernel<<<dim3(8, 384), 256, SMEM_REQ>>>(p_xhi, p_xh8, p_xl8,
                                                    p_wthi, p_wh8, p_wl8,
                                                    b1, p_s, p_V, p_ph);
    gemm96_kernel<2><<<dim3(16, 3, 4), 256>>>(p_ph, W2, p_pooled, b2, nullptr, nullptr);
    final_kernel<<<dim3(NB, 3), 128>>>(p_pooled, ln_g, ln_b, W_last, b_last, out);
}

// round 9
// speedup vs baseline: 1.3847x; 1.3847x over previous
#include <cuda_runtime.h>
#include <cuda_bf16.h>
#include <cstdint>
#include <math.h>

// Problem constants
#define NB   32
#define TLEN 512
#define DDIM 1024
#define CDIM 120
#define NROWS 96
#define INV_SCALE 0.015625f // 1/64
#define TOTROWS 49152
#define BR_STRIDE 16384     // compact rows per branch (max 32*512)

#define NEG_INF __int_as_float(0xff800000)

// ---------------- scratch (device globals) ----------------------------------
__device__ float g_xsum[NROWS * DDIM];
__device__ float g_nv[NROWS];
__device__ float g_u[NROWS * DDIM];
__device__ float g_ub[NROWS];
__device__ float g_v[NROWS * DDIM];
__device__ float g_s[3 * BR_STRIDE];      // compacted scores (per branch)
__device__ float g_attn[3 * BR_STRIDE];   // compacted softmax weights
__device__ int   g_batchof[3 * BR_STRIDE];
__device__ float g_ph[NROWS * DDIM];
__device__ float g_pooled[NROWS * DDIM];
__device__ int   g_rank[NROWS * TLEN];    // local rank within batch, -1 masked
__device__ int   g_V[NROWS];              // valid count per batch-row
__device__ int   g_off[NROWS];            // exclusive offset of batch in branch
__device__ int   g_total[3];              // valid tokens per branch
// split-bf16 operands (globally compacted per branch)
__device__ __nv_bfloat16 g_xhi[(size_t)TOTROWS * DDIM];
__device__ __nv_bfloat16 g_xlo[(size_t)TOTROWS * DDIM];
__device__ __nv_bfloat16 g_w1t_hi[DDIM * DDIM];
__device__ __nv_bfloat16 g_w1t_lo[DDIM * DDIM];

// =================== helpers =================================================
__device__ __forceinline__ void cp16(void* d, const void* s) {
    asm volatile("cp.async.cg.shared.global [%0], [%1], 16;"
                 :: "l"(__cvta_generic_to_shared(d)), "l"(s));
}
__device__ __forceinline__ void cp_commit() {
    asm volatile("cp.async.commit_group;" ::: "memory");
}
__device__ __forceinline__ void cp_wait1() {
    asm volatile("cp.async.wait_group 1;" ::: "memory");
}
__device__ __forceinline__ void cp_wait0() {
    asm volatile("cp.async.wait_group 0;" ::: "memory");
}
__device__ __forceinline__ void mma_bf16(float* d, const uint32_t* a, const uint32_t* b) {
    asm volatile(
        "mma.sync.aligned.m16n8k16.row.col.f32.bf16.bf16.f32 "
        "{%0,%1,%2,%3}, {%4,%5,%6,%7}, {%8,%9}, {%0,%1,%2,%3};"
        : "+f"(d[0]), "+f"(d[1]), "+f"(d[2]), "+f"(d[3])
        : "r"(a[0]), "r"(a[1]), "r"(a[2]), "r"(a[3]), "r"(b[0]), "r"(b[1]));
}
__device__ __forceinline__ void ldm4(uint32_t* r, uint32_t saddr) {
    asm volatile("ldmatrix.sync.aligned.m8n8.x4.shared.b16 {%0,%1,%2,%3}, [%4];"
                 : "=r"(r[0]), "=r"(r[1]), "=r"(r[2]), "=r"(r[3]) : "r"(saddr));
}

// SMEM layout of big kernel: 2 stages x 40960B (M=128 x N=128 x K=32)
#define STAGE_B   40960
#define PLANE_B   10240
#define ROW_B     80
#define OFF_ATT   81920   // 128 floats
#define OFF_BAT   82432   // 128 ints
#define OFF_B1    82944   // 128 floats
#define OFF_COL   83456   // 128 floats
#define SMEM_REQ  83968

// ---------------- K0: zero scratch + conv W1 (fused) ------------------------
__global__ void combo_kernel(const float* __restrict__ W1,
                             __nv_bfloat16* __restrict__ th,
                             __nv_bfloat16* __restrict__ tl,
                             float* __restrict__ ph, float* __restrict__ xsum,
                             float* __restrict__ u, float* __restrict__ v,
                             float* __restrict__ pooled, float* __restrict__ ub,
                             float* __restrict__ attn) {
    int bx = blockIdx.x;
    if (bx < 384) {
        int i = bx * 256 + threadIdx.x;   // covers 98304
        ph[i] = 0.f; xsum[i] = 0.f; u[i] = 0.f; v[i] = 0.f; pooled[i] = 0.f;
        if (i < NROWS) ub[i] = 0.f;
        if (i < 3 * BR_STRIDE) attn[i] = 0.f;
    } else {
        __shared__ float tile[32][33];
        int b = bx - 384;
        int n0 = (b & 31) * 32, k0 = (b >> 5) * 32;
        int tx = threadIdx.x & 31, ty = threadIdx.x >> 5;
        for (int r = ty; r < 32; r += 8)
            tile[r][tx] = W1[(size_t)(k0 + r) * DDIM + n0 + tx];
        __syncthreads();
        for (int r = ty; r < 32; r += 8) {
            float w = tile[tx][r];  // = W1[k0+tx][n0+r]
            __nv_bfloat16 h = __float2bfloat16(w);
            __nv_bfloat16 l = __float2bfloat16(w - __bfloat162float(h));
            size_t o = (size_t)(n0 + r) * DDIM + k0 + tx;
            th[o] = h; tl[o] = l;
        }
    }
}

// ---------------- K0b: mask scan -> rank/V/nv --------------------------------
__global__ void mask_scan_kernel(const int* __restrict__ m0, const int* __restrict__ m1,
                                 const int* __restrict__ m2,
                                 int* __restrict__ rank, int* __restrict__ V,
                                 float* __restrict__ nv) {
    int b = blockIdx.x, br = blockIdx.y;
    const int* M = ((br == 0) ? m0 : (br == 1) ? m1 : m2) + (size_t)b * TLEN;
    int row = br * NB + b;
    int tid = threadIdx.x;  // 512
    __shared__ int ps[TLEN];
    int valid = (M[tid] == 0) ? 1 : 0;
    ps[tid] = valid;
    __syncthreads();
    for (int off = 1; off < TLEN; off <<= 1) {
        int vv = (tid >= off) ? ps[tid - off] : 0;
        __syncthreads();
        ps[tid] += vv;
        __syncthreads();
    }
    rank[row * TLEN + tid] = valid ? (ps[tid] - 1) : -1;
    if (tid == TLEN - 1) {
        V[row] = ps[TLEN - 1];
        nv[row] = (float)ps[TLEN - 1];
    }
}

// ---------------- K0c: per-branch offsets (warp scan over 32 batches) -------
__global__ void offsets_kernel(const int* __restrict__ V, int* __restrict__ off,
                               int* __restrict__ total) {
    int tid = threadIdx.x;   // 96
    if (tid >= 96) return;
    int br = tid >> 5, lane = tid & 31;
    int v = V[br * 32 + lane];
    int s = v;
#pragma unroll
    for (int o = 1; o < 32; o <<= 1) {
        int t = __shfl_up_sync(0xffffffffu, s, o);
        if (lane >= o) s += t;
    }
    off[br * 32 + lane] = s - v;
    if (lane == 31) total[br] = s;
}

// ---------------- K0d: batch-of per compact row + pad fill -------------------
__global__ void fill_batch_kernel(const int* __restrict__ rank,
                                  const int* __restrict__ off,
                                  const int* __restrict__ total,
                                  int* __restrict__ batchof) {
    int b = blockIdx.x, br = blockIdx.y;
    int row = br * NB + b;
    int tid = threadIdx.x;  // 512
    int rk = rank[row * TLEN + tid];
    if (rk >= 0) batchof[br * BR_STRIDE + off[row] + rk] = b;
    if (b == NB - 1) {
        int tot = total[br];
        int up = (tot + 127) & ~127;
        for (int i = tid; i < up - tot; i += 512)
            batchof[br * BR_STRIDE + tot + i] = NB - 1;
    }
}

// ---------------- fused: valid x -> globally compacted bf16 hi/lo + sum -----
// grid (16, 32, 3): 32-token chunks.
__global__ void convsum_kernel(const float* __restrict__ x0, const float* __restrict__ x1,
                               const float* __restrict__ x2,
                               const int* __restrict__ rank,
                               const int* __restrict__ off,
                               __nv_bfloat16* __restrict__ xhi,
                               __nv_bfloat16* __restrict__ xlo,
                               float* __restrict__ xsum) {
    int ch = blockIdx.x, b = blockIdx.y, br = blockIdx.z;
    const float* X = (br == 0) ? x0 : (br == 1) ? x1 : x2;
    int row = br * NB + b;
    __shared__ int smr[32];
    __shared__ int soff;
    int tid = threadIdx.x;
    if (tid < 32) smr[tid] = rank[row * TLEN + ch * 32 + tid];
    if (tid == 0) soff = off[row];
    __syncthreads();

    const float* xp = X + ((size_t)b * TLEN + ch * 32) * DDIM + tid * 4;
    size_t cbase = (size_t)br * BR_STRIDE + soff;
    float ax = 0.f, ay = 0.f, az = 0.f, aw = 0.f;
    for (int t = 0; t < 32; t++) {
        int rk = smr[t];
        if (rk >= 0) {
            float4 v = *(const float4*)(xp + (size_t)t * DDIM);
            __nv_bfloat16 h0 = __float2bfloat16(v.x);
            __nv_bfloat16 h1 = __float2bfloat16(v.y);
            __nv_bfloat16 h2 = __float2bfloat16(v.z);
            __nv_bfloat16 h3 = __float2bfloat16(v.w);
            __nv_bfloat16 l0 = __float2bfloat16(v.x - __bfloat162float(h0));
            __nv_bfloat16 l1 = __float2bfloat16(v.y - __bfloat162float(h1));
            __nv_bfloat16 l2 = __float2bfloat16(v.z - __bfloat162float(h2));
            __nv_bfloat16 l3 = __float2bfloat16(v.w - __bfloat162float(h3));
            size_t o = (cbase + rk) * DDIM + tid * 4;
            __nv_bfloat162* ph2 = (__nv_bfloat162*)(xhi + o);
            __nv_bfloat162* pl2 = (__nv_bfloat162*)(xlo + o);
            ph2[0] = __nv_bfloat162(h0, h1); ph2[1] = __nv_bfloat162(h2, h3);
            pl2[0] = __nv_bfloat162(l0, l1); pl2[1] = __nv_bfloat162(l2, l3);
            ax += v.x; ay += v.y; az += v.z; aw += v.w;
        }
    }
    float* xr = xsum + (size_t)row * DDIM + tid * 4;
    atomicAdd(xr + 0, ax);
    atomicAdd(xr + 1, ay);
    atomicAdd(xr + 2, az);
    atomicAdd(xr + 3, aw);
}

// ---------------- small GEMM, K-split x8: (96 x 1024) @ (1024 x 1024) -------
template <int MODE>
__global__ void gemm96_kernel(const float* __restrict__ A, const float* __restrict__ B,
                              float* __restrict__ C, const float* __restrict__ bias,
                              const float* __restrict__ nv, float* __restrict__ ub) {
    const int BK = 32;
    __shared__ float As[32][BK + 1];
    __shared__ float Bs[BK][64 + 1];
    int m0 = blockIdx.y * 32;
    int n0 = blockIdx.x * 64;
    int ks = blockIdx.z * 128;
    int tid = threadIdx.x;
    int tx = tid & 15, ty = tid >> 4;
    int lane = tid & 31;

    float acc[2][4] = {{0.f, 0.f, 0.f, 0.f}, {0.f, 0.f, 0.f, 0.f}};

    for (int k0 = ks; k0 < ks + 128; k0 += BK) {
#pragma unroll
        for (int i = 0; i < 4; i++) {
            int l = tid + i * 256;
            int r = l >> 5, k = l & 31;
            As[r][k] = A[(size_t)(m0 + r) * DDIM + k0 + k];
        }
        if (MODE == 1) {
#pragma unroll
            for (int i = 0; i < 8; i++) {
                int l = tid + i * 256;
                int kk = l & 31, n = l >> 5;
                Bs[kk][n] = B[(size_t)(n0 + n) * DDIM + k0 + kk];
            }
        } else {
#pragma unroll
            for (int i = 0; i < 8; i++) {
                int l = tid + i * 256;
                int kk = l >> 6, n = l & 63;
                Bs[kk][n] = B[(size_t)(k0 + kk) * DDIM + n0 + n];
            }
        }
        __syncthreads();
#pragma unroll
        for (int kk = 0; kk < BK; kk++) {
            float a0 = As[ty * 2 + 0][kk];
            float a1 = As[ty * 2 + 1][kk];
#pragma unroll
            for (int j = 0; j < 4; j++) {
                float bv = Bs[kk][tx * 4 + j];
                acc[0][j] += a0 * bv;
                acc[1][j] += a1 * bv;
            }
        }
        __syncthreads();
    }

    float vv[2][4];
#pragma unroll
    for (int i = 0; i < 2; i++) {
        int r = m0 + ty * 2 + i;
#pragma unroll
        for (int j = 0; j < 4; j++) {
            int c = n0 + tx * 4 + j;
            float v = acc[i][j];
            if (MODE == 0 && blockIdx.z == 0) v += nv[r] * bias[c];
            if (MODE == 2 && blockIdx.z == 0) v += bias[c];
            vv[i][j] = v;
            atomicAdd(&C[(size_t)r * DDIM + c], v);
        }
    }
    if (MODE == 0) {
        float u0 = 0.f, u1 = 0.f;
#pragma unroll
        for (int j = 0; j < 4; j++) {
            float ba = bias[n0 + tx * 4 + j];
            u0 += vv[0][j] * ba;
            u1 += vv[1][j] * ba;
        }
#pragma unroll
        for (int o = 8; o > 0; o >>= 1) {
            u0 += __shfl_xor_sync(0xffffffffu, u0, o);
            u1 += __shfl_xor_sync(0xffffffffu, u1, o);
        }
        if ((lane & 15) == 0) {
            atomicAdd(&ub[m0 + ty * 2 + 0], u0);
            atomicAdd(&ub[m0 + ty * 2 + 1], u1);
        }
    }
}

// ---------------- K3: compacted s[branch][off+rank] --------------------------
__global__ void s_kernel(const float* __restrict__ x0, const float* __restrict__ x1,
                         const float* __restrict__ x2,
                         const int* __restrict__ rank, const int* __restrict__ off,
                         const float* __restrict__ v, const float* __restrict__ ub,
                         float* __restrict__ s) {
    int br = blockIdx.z, b = blockIdx.y;
    int w = threadIdx.x >> 5, lane = threadIdx.x & 31;
    int t = blockIdx.x * 8 + w;
    const float* X = (br == 0) ? x0 : (br == 1) ? x1 : x2;
    int row = br * NB + b;
    int rk = rank[row * TLEN + t];
    if (rk < 0) return;
    const float* xr = X + ((size_t)b * TLEN + t) * DDIM;
    const float* vr = v + (size_t)row * DDIM;
    float acc = 0.f;
#pragma unroll
    for (int i = 0; i < 8; i++) {
        int d = lane * 4 + i * 128;
        float4 xv = *(const float4*)&xr[d];
        float4 vv = *(const float4*)&vr[d];
        acc += xv.x * vv.x + xv.y * vv.y + xv.z * vv.z + xv.w * vv.w;
    }
#pragma unroll
    for (int o = 16; o > 0; o >>= 1) acc += __shfl_xor_sync(0xffffffffu, acc, o);
    if (lane == 0) s[br * BR_STRIDE + off[row] + rk] = (acc + ub[row]) * INV_SCALE;
}

// ---------------- K4: softmax over compact segment [off, off+V) -------------
__global__ void softmax_kernel(const float* __restrict__ s, const int* __restrict__ off,
                               const int* __restrict__ V, float* __restrict__ attn) {
    int b = blockIdx.x, br = blockIdx.y;
    int row = br * NB + b;
    int base = br * BR_STRIDE + off[row];
    int Vr = V[row];
    int tid = threadIdx.x;  // 256
    __shared__ float red[256];
    float v0 = (tid < Vr) ? s[base + tid] : NEG_INF;
    float v1 = (tid + 256 < Vr) ? s[base + tid + 256] : NEG_INF;
    red[tid] = fmaxf(v0, v1);
    __syncthreads();
    for (int st = 128; st > 0; st >>= 1) {
        if (tid < st) red[tid] = fmaxf(red[tid], red[tid + st]);
        __syncthreads();
    }
    float mx = red[0];
    __syncthreads();
    float e0 = (tid < Vr) ? expf(v0 - mx) : 0.f;
    float e1 = (tid + 256 < Vr) ? expf(v1 - mx) : 0.f;
    red[tid] = e0 + e1;
    __syncthreads();
    for (int st = 128; st > 0; st >>= 1) {
        if (tid < st) red[tid] += red[tid + st];
        __syncthreads();
    }
    float inv = 1.0f / red[0];
    if (tid < Vr) attn[base + tid] = e0 * inv;
    if (tid + 256 < Vr) attn[base + tid + 256] = e1 * inv;
}

// ---------------- K5: split-bf16 mma GEMM over globally compacted rows ------
// grid (8, 384): bx = N-block; branch = by>>7, tile = by&127.
__global__ __launch_bounds__(256, 2) void big_mma_kernel(
    const __nv_bfloat16* __restrict__ xhi, const __nv_bfloat16* __restrict__ xlo,
    const __nv_bfloat16* __restrict__ wth, const __nv_bfloat16* __restrict__ wtl,
    const float* __restrict__ b1, const float* __restrict__ attn,
    const int* __restrict__ batchof, const int* __restrict__ total,
    float* __restrict__ ph) {
    extern __shared__ __align__(16) char smc[];
    float* att_s = (float*)(smc + OFF_ATT);
    int*   bat_s = (int*)(smc + OFF_BAT);
    float* b1s   = (float*)(smc + OFF_B1);
    float* cols  = (float*)(smc + OFF_COL);
    uint32_t sbase = (uint32_t)__cvta_generic_to_shared(smc);

    int by = blockIdx.y;
    int branch = by >> 7, tile = by & 127;
    if (tile * 128 >= total[branch]) return;

    int tid = threadIdx.x;
    int wid = tid >> 5, lane = tid & 31;
    int wm = wid >> 2, wn = wid & 3;
    int g = lane >> 2, tg = lane & 3;
    int n0 = blockIdx.x * 128;
    size_t rowbase = (size_t)branch * BR_STRIDE + tile * 128;

    auto load_stage = [&](int st) {
        char* buf = smc + (st & 1) * STAGE_B;
        int k0 = st * 32;
#pragma unroll
        for (int c = tid; c < 512; c += 256) {
            int r = c >> 2, j = c & 3;
            int off = r * ROW_B + j * 16;
            size_t asrc = (rowbase + r) * DDIM + k0 + j * 8;
            size_t bsrc = (size_t)(n0 + r) * DDIM + k0 + j * 8;
            cp16(buf + off, xhi + asrc);
            cp16(buf + PLANE_B + off, xlo + asrc);
            cp16(buf + 2 * PLANE_B + off, wth + bsrc);
            cp16(buf + 3 * PLANE_B + off, wtl + bsrc);
        }
    };

    load_stage(0); cp_commit();

    if (tid < 128) {
        att_s[tid] = attn[rowbase + tid];
        bat_s[tid] = batchof[rowbase + tid];
        b1s[tid] = b1[n0 + tid];
    }

    float acc[4][4][4];
#pragma unroll
    for (int mi = 0; mi < 4; mi++)
#pragma unroll
        for (int ni = 0; ni < 4; ni++)
#pragma unroll
            for (int j = 0; j < 4; j++) acc[mi][ni][j] = 0.f;

    uint32_t a_l = (uint32_t)((wm * 64 + (lane & 15)) * ROW_B + (lane >> 4) * 16);
    uint32_t b_l = (uint32_t)((wn * 32 + (lane & 7) + ((lane >> 4) << 3)) * ROW_B +
                              ((lane >> 3) & 1) * 16);

    for (int st = 0; st < 32; ++st) {
        if (st + 1 < 32) { load_stage(st + 1); cp_commit(); cp_wait1(); }
        else            { cp_wait0(); }
        __syncthreads();
        uint32_t buf = sbase + (uint32_t)(st & 1) * STAGE_B;
#pragma unroll
        for (int ksub = 0; ksub < 2; ++ksub) {
            uint32_t aoff = buf + a_l + (uint32_t)ksub * 32u;
            uint32_t boff = buf + 2u * PLANE_B + b_l + (uint32_t)ksub * 32u;
            uint32_t a[4][4], bh[2][4], bl[2][4];
#pragma unroll
            for (int mi = 0; mi < 4; mi++) ldm4(a[mi], aoff + mi * (16 * ROW_B));
#pragma unroll
            for (int p = 0; p < 2; p++) {
                ldm4(bh[p], boff + p * (16 * ROW_B));
                ldm4(bl[p], boff + PLANE_B + p * (16 * ROW_B));
            }
#pragma unroll
            for (int mi = 0; mi < 4; mi++)
#pragma unroll
                for (int ni = 0; ni < 4; ni++) {
                    mma_bf16(acc[mi][ni], a[mi], &bh[ni >> 1][(ni & 1) * 2]);
                    mma_bf16(acc[mi][ni], a[mi], &bl[ni >> 1][(ni & 1) * 2]);
                }
            // lo-plane A reuses the a registers
#pragma unroll
            for (int mi = 0; mi < 4; mi++)
                ldm4(a[mi], aoff + PLANE_B + mi * (16 * ROW_B));
#pragma unroll
            for (int mi = 0; mi < 4; mi++)
#pragma unroll
                for (int ni = 0; ni < 4; ni++)
                    mma_bf16(acc[mi][ni], a[mi], &bh[ni >> 1][(ni & 1) * 2]);
        }
        __syncthreads();
    }

    // ---- segmented epilogue: per batch present in this tile -----------------
    int batch0 = bat_s[0];
    int nseg = bat_s[127] - batch0 + 1;
    for (int sg = 0; sg < nseg; ++sg) {
        int bsel = batch0 + sg;
        if (tid < 128) cols[tid] = 0.f;
        __syncthreads();
#pragma unroll
        for (int mi = 0; mi < 4; mi++) {
            int rA = wm * 64 + mi * 16 + g;
            float wA = (bat_s[rA] == bsel) ? att_s[rA] : 0.f;
            float wB = (bat_s[rA + 8] == bsel) ? att_s[rA + 8] : 0.f;
#pragma unroll
            for (int ni = 0; ni < 4; ni++) {
                int c0 = wn * 32 + ni * 8 + tg * 2;
                float bv0 = b1s[c0], bv1 = b1s[c0 + 1];
                float v0 = fmaxf(acc[mi][ni][0] + bv0, 0.f) * wA +
                           fmaxf(acc[mi][ni][2] + bv0, 0.f) * wB;
                float v1 = fmaxf(acc[mi][ni][1] + bv1, 0.f) * wA +
                           fmaxf(acc[mi][ni][3] + bv1, 0.f) * wB;
#pragma unroll
                for (int o = 4; o <= 16; o <<= 1) {
                    v0 += __shfl_xor_sync(0xffffffffu, v0, o);
                    v1 += __shfl_xor_sync(0xffffffffu, v1, o);
                }
                if (g == 0) {
                    atomicAdd(&cols[c0], v0);
                    atomicAdd(&cols[c0 + 1], v1);
                }
            }
        }
        __syncthreads();
        if (tid < 128 && bsel < NB)
            atomicAdd(&ph[((size_t)(branch * NB + bsel)) * DDIM + n0 + tid], cols[tid]);
        __syncthreads();
    }
}

// ---------------- K6: layernorm + relu + last linear -----------------------
__global__ void final_kernel(const float* __restrict__ pooled,
                             const float* __restrict__ ln_g, const float* __restrict__ ln_b,
                             const float* __restrict__ W_last, const float* __restrict__ b_last,
                             float* __restrict__ out) {
    int row = blockIdx.y * NB + blockIdx.x;
    int tid = threadIdx.x;
    __shared__ float act[DDIM];
    __shared__ float red[128];

    float vals[8];
    float lsum = 0.f;
#pragma unroll
    for (int i = 0; i < 8; i++) {
        vals[i] = pooled[(size_t)row * DDIM + tid + i * 128];
        lsum += vals[i];
    }
    red[tid] = lsum;
    __syncthreads();
    for (int s = 64; s > 0; s >>= 1) {
        if (tid < s) red[tid] += red[tid + s];
        __syncthreads();
    }
    float mu = red[0] * (1.0f / DDIM);
    __syncthreads();
    float lsq = 0.f;
#pragma unroll
    for (int i = 0; i < 8; i++) {
        float d = vals[i] - mu;
        lsq += d * d;
    }
    red[tid] = lsq;
    __syncthreads();
    for (int s = 64; s > 0; s >>= 1) {
        if (tid < s) red[tid] += red[tid + s];
        __syncthreads();
    }
    float var = red[0] * (1.0f / DDIM);
    float vv = var + 1e-12f;
    float inv = rsqrtf(vv);
    inv = inv * (1.5f - 0.5f * vv * inv * inv);
    __syncthreads();
#pragma unroll
    for (int i = 0; i < 8; i++) {
        int d = tid + i * 128;
        float nvv = (vals[i] - mu) * inv * ln_g[d] + ln_b[d];
        act[d] = fmaxf(nvv, 0.f);
    }
    __syncthreads();
    if (tid < CDIM) {
        float accv = b_last[tid];
        for (int d = 0; d < DDIM; d++) accv += act[d] * W_last[(size_t)d * CDIM + tid];
        out[(size_t)row * CDIM + tid] = accv;
    }
}

// ---------------- launch ----------------------------------------------------
extern "C" void kernel_launch(void* const* d_in, const int* in_sizes, int n_in,
                              void* d_out, int out_size) {
    const float* x0 = (const float*)d_in[0];
    const float* x1 = (const float*)d_in[1];
    const float* x2 = (const float*)d_in[2];
    const int* m0 = (const int*)d_in[3];
    const int* m1 = (const int*)d_in[4];
    const int* m2 = (const int*)d_in[5];
    const float* W_attn = (const float*)d_in[6];
    const float* b_attn = (const float*)d_in[7];
    const float* W1 = (const float*)d_in[8];
    const float* b1 = (const float*)d_in[9];
    const float* W2 = (const float*)d_in[10];
    const float* b2 = (const float*)d_in[11];
    const float* ln_g = (const float*)d_in[12];
    const float* ln_b = (const float*)d_in[13];
    const float* W_last = (const float*)d_in[14];
    const float* b_last = (const float*)d_in[15];
    float* out = (float*)d_out;

    float *p_xsum, *p_nv, *p_u, *p_ub, *p_v, *p_s, *p_attn, *p_ph, *p_pooled;
    int *p_rank, *p_V, *p_off, *p_total, *p_batchof;
    __nv_bfloat16 *p_xhi, *p_xlo, *p_wth, *p_wtl;
    cudaGetSymbolAddress((void**)&p_xsum, g_xsum);
    cudaGetSymbolAddress((void**)&p_nv, g_nv);
    cudaGetSymbolAddress((void**)&p_u, g_u);
    cudaGetSymbolAddress((void**)&p_ub, g_ub);
    cudaGetSymbolAddress((void**)&p_v, g_v);
    cudaGetSymbolAddress((void**)&p_s, g_s);
    cudaGetSymbolAddress((void**)&p_attn, g_attn);
    cudaGetSymbolAddress((void**)&p_ph, g_ph);
    cudaGetSymbolAddress((void**)&p_pooled, g_pooled);
    cudaGetSymbolAddress((void**)&p_rank, g_rank);
    cudaGetSymbolAddress((void**)&p_V, g_V);
    cudaGetSymbolAddress((void**)&p_off, g_off);
    cudaGetSymbolAddress((void**)&p_total, g_total);
    cudaGetSymbolAddress((void**)&p_batchof, g_batchof);
    cudaGetSymbolAddress((void**)&p_xhi, g_xhi);
    cudaGetSymbolAddress((void**)&p_xlo, g_xlo);
    cudaGetSymbolAddress((void**)&p_wth, g_w1t_hi);
    cudaGetSymbolAddress((void**)&p_wtl, g_w1t_lo);

    cudaFuncSetAttribute(big_mma_kernel, cudaFuncAttributeMaxDynamicSharedMemorySize,
                         SMEM_REQ);

    combo_kernel<<<1408, 256>>>(W1, p_wth, p_wtl, p_ph, p_xsum, p_u, p_v,
                                p_pooled, p_ub, p_attn);
    mask_scan_kernel<<<dim3(NB, 3), 512>>>(m0, m1, m2, p_rank, p_V, p_nv);
    offsets_kernel<<<1, 96>>>(p_V, p_off, p_total);
    convsum_kernel<<<dim3(16, NB, 3), 256>>>(x0, x1, x2, p_rank, p_off,
                                             p_xhi, p_xlo, p_xsum);
    fill_batch_kernel<<<dim3(NB, 3), 512>>>(p_rank, p_off, p_total, p_batchof);
    gemm96_kernel<0><<<dim3(16, 3, 8), 256>>>(p_xsum, W_attn, p_u, b_attn, p_nv, p_ub);
    gemm96_kernel<1><<<dim3(16, 3, 8), 256>>>(p_u, W_attn, p_v, nullptr, nullptr, nullptr);
    s_kernel<<<dim3(64, NB, 3), 256>>>(x0, x1, x2, p_rank, p_off, p_v, p_ub, p_s);
    softmax_kernel<<<dim3(NB, 3), 256>>>(p_s, p_off, p_V, p_attn);
    big_mma_kernel<<<dim3(8, 384), 256, SMEM_REQ>>>(p_xhi, p_xlo, p_wth, p_wtl,
                                                    b1, p_attn, p_batchof, p_total, p_ph);
    gemm96_kernel<2><<<dim3(16, 3, 8), 256>>>(p_ph, W2, p_pooled, b2, nullptr, nullptr);
    final_kernel<<<dim3(NB, 3), 128>>>(p_pooled, ln_g, ln_b, W_last, b_last, out);
}

// round 10
// speedup vs baseline: 1.3927x; 1.0057x over previous
#include <cuda_runtime.h>
#include <cuda_bf16.h>
#include <cstdint>
#include <math.h>

// Problem constants
#define NB   32
#define TLEN 512
#define DDIM 1024
#define CDIM 120
#define NROWS 96
#define INV_SCALE 0.015625f // 1/64
#define TOTROWS 49152
#define BR_STRIDE 16384     // compact rows per branch (max 32*512)

#define NEG_INF __int_as_float(0xff800000)

// ---------------- scratch (device globals) ----------------------------------
__device__ float g_xsum[NROWS * DDIM];
__device__ float g_nv[NROWS];
__device__ float g_u[NROWS * DDIM];
__device__ float g_ub[NROWS];
__device__ float g_v[NROWS * DDIM];
__device__ float g_s[3 * BR_STRIDE];      // compacted scores (per branch)
__device__ float g_attn[3 * BR_STRIDE];   // compacted softmax weights
__device__ int   g_batchof[3 * BR_STRIDE];
__device__ float g_ph[NROWS * DDIM];
__device__ float g_pooled[NROWS * DDIM];
__device__ int   g_rank[NROWS * TLEN];    // local rank within batch, -1 masked
__device__ int   g_V[NROWS];              // valid count per batch-row
__device__ int   g_off[NROWS];            // exclusive offset of batch in branch
__device__ int   g_total[3];              // valid tokens per branch
// split-bf16 operands (globally compacted per branch)
__device__ __nv_bfloat16 g_xhi[(size_t)TOTROWS * DDIM];
__device__ __nv_bfloat16 g_xlo[(size_t)TOTROWS * DDIM];
__device__ __nv_bfloat16 g_w1t_hi[DDIM * DDIM];
__device__ __nv_bfloat16 g_w1t_lo[DDIM * DDIM];

// =================== helpers =================================================
__device__ __forceinline__ void cp16(void* d, const void* s) {
    asm volatile("cp.async.cg.shared.global [%0], [%1], 16;"
                 :: "l"(__cvta_generic_to_shared(d)), "l"(s));
}
__device__ __forceinline__ void cp_commit() {
    asm volatile("cp.async.commit_group;" ::: "memory");
}
__device__ __forceinline__ void cp_wait1() {
    asm volatile("cp.async.wait_group 1;" ::: "memory");
}
__device__ __forceinline__ void cp_wait0() {
    asm volatile("cp.async.wait_group 0;" ::: "memory");
}
__device__ __forceinline__ void mma_bf16(float* d, const uint32_t* a, const uint32_t* b) {
    asm volatile(
        "mma.sync.aligned.m16n8k16.row.col.f32.bf16.bf16.f32 "
        "{%0,%1,%2,%3}, {%4,%5,%6,%7}, {%8,%9}, {%0,%1,%2,%3};"
        : "+f"(d[0]), "+f"(d[1]), "+f"(d[2]), "+f"(d[3])
        : "r"(a[0]), "r"(a[1]), "r"(a[2]), "r"(a[3]), "r"(b[0]), "r"(b[1]));
}
__device__ __forceinline__ void ldm4(uint32_t* r, uint32_t saddr) {
    asm volatile("ldmatrix.sync.aligned.m8n8.x4.shared.b16 {%0,%1,%2,%3}, [%4];"
                 : "=r"(r[0]), "=r"(r[1]), "=r"(r[2]), "=r"(r[3]) : "r"(saddr));
}

// SMEM layout of big kernel: 2 stages x 40960B (M=128 x N=128 x K=32)
#define STAGE_B   40960
#define PLANE_B   10240
#define ROW_B     80
#define OFF_ATT   81920   // 128 floats
#define OFF_BAT   82432   // 128 ints
#define OFF_B1    82944   // 128 floats
#define OFF_COL   83456   // 128 floats
#define SMEM_REQ  83968

// ---------------- K0: zero scratch + conv W1 (fused) ------------------------
__global__ void combo_kernel(const float* __restrict__ W1,
                             __nv_bfloat16* __restrict__ th,
                             __nv_bfloat16* __restrict__ tl,
                             float* __restrict__ ph, float* __restrict__ xsum,
                             float* __restrict__ u, float* __restrict__ v,
                             float* __restrict__ pooled, float* __restrict__ ub,
                             float* __restrict__ attn) {
    int bx = blockIdx.x;
    if (bx < 384) {
        int i = bx * 256 + threadIdx.x;   // covers 98304
        ph[i] = 0.f; xsum[i] = 0.f; u[i] = 0.f; v[i] = 0.f; pooled[i] = 0.f;
        if (i < NROWS) ub[i] = 0.f;
        if (i < 3 * BR_STRIDE) attn[i] = 0.f;
    } else {
        __shared__ float tile[32][33];
        int b = bx - 384;
        int n0 = (b & 31) * 32, k0 = (b >> 5) * 32;
        int tx = threadIdx.x & 31, ty = threadIdx.x >> 5;
        for (int r = ty; r < 32; r += 8)
            tile[r][tx] = W1[(size_t)(k0 + r) * DDIM + n0 + tx];
        __syncthreads();
        for (int r = ty; r < 32; r += 8) {
            float w = tile[tx][r];  // = W1[k0+tx][n0+r]
            __nv_bfloat16 h = __float2bfloat16(w);
            __nv_bfloat16 l = __float2bfloat16(w - __bfloat162float(h));
            size_t o = (size_t)(n0 + r) * DDIM + k0 + tx;
            th[o] = h; tl[o] = l;
        }
    }
}

// ---------------- K0b: mask scan -> rank/V/nv --------------------------------
__global__ void mask_scan_kernel(const int* __restrict__ m0, const int* __restrict__ m1,
                                 const int* __restrict__ m2,
                                 int* __restrict__ rank, int* __restrict__ V,
                                 float* __restrict__ nv) {
    int b = blockIdx.x, br = blockIdx.y;
    const int* M = ((br == 0) ? m0 : (br == 1) ? m1 : m2) + (size_t)b * TLEN;
    int row = br * NB + b;
    int tid = threadIdx.x;  // 512
    __shared__ int ps[TLEN];
    int valid = (M[tid] == 0) ? 1 : 0;
    ps[tid] = valid;
    __syncthreads();
    for (int off = 1; off < TLEN; off <<= 1) {
        int vv = (tid >= off) ? ps[tid - off] : 0;
        __syncthreads();
        ps[tid] += vv;
        __syncthreads();
    }
    rank[row * TLEN + tid] = valid ? (ps[tid] - 1) : -1;
    if (tid == TLEN - 1) {
        V[row] = ps[TLEN - 1];
        nv[row] = (float)ps[TLEN - 1];
    }
}

// ---------------- K0c: offsets (warp scan) + pad fill of batchof -------------
__global__ void offsets_kernel(const int* __restrict__ V, int* __restrict__ off,
                               int* __restrict__ total, int* __restrict__ batchof) {
    int tid = threadIdx.x;   // 96
    if (tid >= 96) return;
    int br = tid >> 5, lane = tid & 31;
    int v = V[br * 32 + lane];
    int s = v;
#pragma unroll
    for (int o = 1; o < 32; o <<= 1) {
        int t = __shfl_up_sync(0xffffffffu, s, o);
        if (lane >= o) s += t;
    }
    off[br * 32 + lane] = s - v;
    int tot = __shfl_sync(0xffffffffu, s, 31);
    if (lane == 31) total[br] = tot;
    int up = (tot + 127) & ~127;
    for (int i = tot + lane; i < up; i += 32)
        batchof[br * BR_STRIDE + i] = NB - 1;
}

// ---------------- fused: valid x -> globally compacted bf16 hi/lo + sum -----
// grid (16, 32, 3): 32-token chunks, unroll-2 over tokens for MLP.
__global__ void convsum_kernel(const float* __restrict__ x0, const float* __restrict__ x1,
                               const float* __restrict__ x2,
                               const int* __restrict__ rank,
                               const int* __restrict__ off,
                               __nv_bfloat16* __restrict__ xhi,
                               __nv_bfloat16* __restrict__ xlo,
                               float* __restrict__ xsum, int* __restrict__ batchof) {
    int ch = blockIdx.x, b = blockIdx.y, br = blockIdx.z;
    const float* X = (br == 0) ? x0 : (br == 1) ? x1 : x2;
    int row = br * NB + b;
    __shared__ int smr[32];
    __shared__ int soff;
    int tid = threadIdx.x;
    if (tid < 32) smr[tid] = rank[row * TLEN + ch * 32 + tid];
    if (tid == 0) soff = off[row];
    __syncthreads();
    size_t cbase = (size_t)br * BR_STRIDE + soff;
    if (tid < 32 && smr[tid] >= 0) batchof[cbase + smr[tid]] = b;

    const float* xp = X + ((size_t)b * TLEN + ch * 32) * DDIM + tid * 4;
    float ax = 0.f, ay = 0.f, az = 0.f, aw = 0.f;
#pragma unroll 1
    for (int t = 0; t < 32; t += 2) {
        int rk0 = smr[t], rk1 = smr[t + 1];
        float4 v0, v1;
        if (rk0 >= 0) v0 = *(const float4*)(xp + (size_t)t * DDIM);
        if (rk1 >= 0) v1 = *(const float4*)(xp + (size_t)(t + 1) * DDIM);
        if (rk0 >= 0) {
            __nv_bfloat16 h0 = __float2bfloat16(v0.x);
            __nv_bfloat16 h1 = __float2bfloat16(v0.y);
            __nv_bfloat16 h2 = __float2bfloat16(v0.z);
            __nv_bfloat16 h3 = __float2bfloat16(v0.w);
            size_t o = (cbase + rk0) * DDIM + tid * 4;
            __nv_bfloat162* ph2 = (__nv_bfloat162*)(xhi + o);
            __nv_bfloat162* pl2 = (__nv_bfloat162*)(xlo + o);
            ph2[0] = __nv_bfloat162(h0, h1); ph2[1] = __nv_bfloat162(h2, h3);
            pl2[0] = __nv_bfloat162(__float2bfloat16(v0.x - __bfloat162float(h0)),
                                    __float2bfloat16(v0.y - __bfloat162float(h1)));
            pl2[1] = __nv_bfloat162(__float2bfloat16(v0.z - __bfloat162float(h2)),
                                    __float2bfloat16(v0.w - __bfloat162float(h3)));
            ax += v0.x; ay += v0.y; az += v0.z; aw += v0.w;
        }
        if (rk1 >= 0) {
            __nv_bfloat16 h0 = __float2bfloat16(v1.x);
            __nv_bfloat16 h1 = __float2bfloat16(v1.y);
            __nv_bfloat16 h2 = __float2bfloat16(v1.z);
            __nv_bfloat16 h3 = __float2bfloat16(v1.w);
            size_t o = (cbase + rk1) * DDIM + tid * 4;
            __nv_bfloat162* ph2 = (__nv_bfloat162*)(xhi + o);
            __nv_bfloat162* pl2 = (__nv_bfloat162*)(xlo + o);
            ph2[0] = __nv_bfloat162(h0, h1); ph2[1] = __nv_bfloat162(h2, h3);
            pl2[0] = __nv_bfloat162(__float2bfloat16(v1.x - __bfloat162float(h0)),
                                    __float2bfloat16(v1.y - __bfloat162float(h1)));
            pl2[1] = __nv_bfloat162(__float2bfloat16(v1.z - __bfloat162float(h2)),
                                    __float2bfloat16(v1.w - __bfloat162float(h3)));
            ax += v1.x; ay += v1.y; az += v1.z; aw += v1.w;
        }
    }
    float* xr = xsum + (size_t)row * DDIM + tid * 4;
    atomicAdd(xr + 0, ax);
    atomicAdd(xr + 1, ay);
    atomicAdd(xr + 2, az);
    atomicAdd(xr + 3, aw);
}

// ---------------- small GEMM, K-split x8: (96 x 1024) @ (1024 x 1024) -------
template <int MODE>
__global__ void gemm96_kernel(const float* __restrict__ A, const float* __restrict__ B,
                              float* __restrict__ C, const float* __restrict__ bias,
                              const float* __restrict__ nv, float* __restrict__ ub) {
    const int BK = 32;
    __shared__ float As[32][BK + 1];
    __shared__ float Bs[BK][64 + 1];
    int m0 = blockIdx.y * 32;
    int n0 = blockIdx.x * 64;
    int ks = blockIdx.z * 128;
    int tid = threadIdx.x;
    int tx = tid & 15, ty = tid >> 4;
    int lane = tid & 31;

    float acc[2][4] = {{0.f, 0.f, 0.f, 0.f}, {0.f, 0.f, 0.f, 0.f}};

    for (int k0 = ks; k0 < ks + 128; k0 += BK) {
#pragma unroll
        for (int i = 0; i < 4; i++) {
            int l = tid + i * 256;
            int r = l >> 5, k = l & 31;
            As[r][k] = A[(size_t)(m0 + r) * DDIM + k0 + k];
        }
        if (MODE == 1) {
#pragma unroll
            for (int i = 0; i < 8; i++) {
                int l = tid + i * 256;
                int kk = l & 31, n = l >> 5;
                Bs[kk][n] = B[(size_t)(n0 + n) * DDIM + k0 + kk];
            }
        } else {
#pragma unroll
            for (int i = 0; i < 8; i++) {
                int l = tid + i * 256;
                int kk = l >> 6, n = l & 63;
                Bs[kk][n] = B[(size_t)(k0 + kk) * DDIM + n0 + n];
            }
        }
        __syncthreads();
#pragma unroll
        for (int kk = 0; kk < BK; kk++) {
            float a0 = As[ty * 2 + 0][kk];
            float a1 = As[ty * 2 + 1][kk];
#pragma unroll
            for (int j = 0; j < 4; j++) {
                float bv = Bs[kk][tx * 4 + j];
                acc[0][j] += a0 * bv;
                acc[1][j] += a1 * bv;
            }
        }
        __syncthreads();
    }

    float vv[2][4];
#pragma unroll
    for (int i = 0; i < 2; i++) {
        int r = m0 + ty * 2 + i;
#pragma unroll
        for (int j = 0; j < 4; j++) {
            int c = n0 + tx * 4 + j;
            float v = acc[i][j];
            if (MODE == 0 && blockIdx.z == 0) v += nv[r] * bias[c];
            if (MODE == 2 && blockIdx.z == 0) v += bias[c];
            vv[i][j] = v;
            atomicAdd(&C[(size_t)r * DDIM + c], v);
        }
    }
    if (MODE == 0) {
        float u0 = 0.f, u1 = 0.f;
#pragma unroll
        for (int j = 0; j < 4; j++) {
            float ba = bias[n0 + tx * 4 + j];
            u0 += vv[0][j] * ba;
            u1 += vv[1][j] * ba;
        }
#pragma unroll
        for (int o = 8; o > 0; o >>= 1) {
            u0 += __shfl_xor_sync(0xffffffffu, u0, o);
            u1 += __shfl_xor_sync(0xffffffffu, u1, o);
        }
        if ((lane & 15) == 0) {
            atomicAdd(&ub[m0 + ty * 2 + 0], u0);
            atomicAdd(&ub[m0 + ty * 2 + 1], u1);
        }
    }
}

// ---------------- K3: compacted s[branch][off+rank] --------------------------
__global__ void s_kernel(const float* __restrict__ x0, const float* __restrict__ x1,
                         const float* __restrict__ x2,
                         const int* __restrict__ rank, const int* __restrict__ off,
                         const float* __restrict__ v, const float* __restrict__ ub,
                         float* __restrict__ s) {
    int br = blockIdx.z, b = blockIdx.y;
    int w = threadIdx.x >> 5, lane = threadIdx.x & 31;
    int t = blockIdx.x * 8 + w;
    const float* X = (br == 0) ? x0 : (br == 1) ? x1 : x2;
    int row = br * NB + b;
    int rk = rank[row * TLEN + t];
    if (rk < 0) return;
    const float* xr = X + ((size_t)b * TLEN + t) * DDIM;
    const float* vr = v + (size_t)row * DDIM;
    float acc = 0.f;
#pragma unroll
    for (int i = 0; i < 8; i++) {
        int d = lane * 4 + i * 128;
        float4 xv = *(const float4*)&xr[d];
        float4 vv = *(const float4*)&vr[d];
        acc += xv.x * vv.x + xv.y * vv.y + xv.z * vv.z + xv.w * vv.w;
    }
#pragma unroll
    for (int o = 16; o > 0; o >>= 1) acc += __shfl_xor_sync(0xffffffffu, acc, o);
    if (lane == 0) s[br * BR_STRIDE + off[row] + rk] = (acc + ub[row]) * INV_SCALE;
}

// ---------------- K4: softmax over compact segment [off, off+V) -------------
__global__ void softmax_kernel(const float* __restrict__ s, const int* __restrict__ off,
                               const int* __restrict__ V, float* __restrict__ attn) {
    int b = blockIdx.x, br = blockIdx.y;
    int row = br * NB + b;
    int base = br * BR_STRIDE + off[row];
    int Vr = V[row];
    int tid = threadIdx.x;  // 256
    __shared__ float red[256];
    float v0 = (tid < Vr) ? s[base + tid] : NEG_INF;
    float v1 = (tid + 256 < Vr) ? s[base + tid + 256] : NEG_INF;
    red[tid] = fmaxf(v0, v1);
    __syncthreads();
    for (int st = 128; st > 0; st >>= 1) {
        if (tid < st) red[tid] = fmaxf(red[tid], red[tid + st]);
        __syncthreads();
    }
    float mx = red[0];
    __syncthreads();
    float e0 = (tid < Vr) ? expf(v0 - mx) : 0.f;
    float e1 = (tid + 256 < Vr) ? expf(v1 - mx) : 0.f;
    red[tid] = e0 + e1;
    __syncthreads();
    for (int st = 128; st > 0; st >>= 1) {
        if (tid < st) red[tid] += red[tid + st];
        __syncthreads();
    }
    float inv = 1.0f / red[0];
    if (tid < Vr) attn[base + tid] = e0 * inv;
    if (tid + 256 < Vr) attn[base + tid + 256] = e1 * inv;
}

// ---------------- K5: split-bf16 mma GEMM over globally compacted rows ------
// grid (8, 384): bx = N-block; branch = by>>7, tile = by&127.
// Full fragment prefetch per ksub; segmented epilogue with relu precompute.
__global__ __launch_bounds__(256, 2) void big_mma_kernel(
    const __nv_bfloat16* __restrict__ xhi, const __nv_bfloat16* __restrict__ xlo,
    const __nv_bfloat16* __restrict__ wth, const __nv_bfloat16* __restrict__ wtl,
    const float* __restrict__ b1, const float* __restrict__ attn,
    const int* __restrict__ batchof, const int* __restrict__ total,
    float* __restrict__ ph) {
    extern __shared__ __align__(16) char smc[];
    float* att_s = (float*)(smc + OFF_ATT);
    int*   bat_s = (int*)(smc + OFF_BAT);
    float* b1s   = (float*)(smc + OFF_B1);
    float* cols  = (float*)(smc + OFF_COL);
    uint32_t sbase = (uint32_t)__cvta_generic_to_shared(smc);

    int by = blockIdx.y;
    int branch = by >> 7, tile = by & 127;
    if (tile * 128 >= total[branch]) return;

    int tid = threadIdx.x;
    int wid = tid >> 5, lane = tid & 31;
    int wm = wid >> 2, wn = wid & 3;
    int g = lane >> 2, tg = lane & 3;
    int n0 = blockIdx.x * 128;
    size_t rowbase = (size_t)branch * BR_STRIDE + tile * 128;

    auto load_stage = [&](int st) {
        char* buf = smc + (st & 1) * STAGE_B;
        int k0 = st * 32;
#pragma unroll
        for (int c = tid; c < 512; c += 256) {
            int r = c >> 2, j = c & 3;
            int off = r * ROW_B + j * 16;
            size_t asrc = (rowbase + r) * DDIM + k0 + j * 8;
            size_t bsrc = (size_t)(n0 + r) * DDIM + k0 + j * 8;
            cp16(buf + off, xhi + asrc);
            cp16(buf + PLANE_B + off, xlo + asrc);
            cp16(buf + 2 * PLANE_B + off, wth + bsrc);
            cp16(buf + 3 * PLANE_B + off, wtl + bsrc);
        }
    };

    load_stage(0); cp_commit();

    if (tid < 128) {
        att_s[tid] = attn[rowbase + tid];
        bat_s[tid] = batchof[rowbase + tid];
        b1s[tid] = b1[n0 + tid];
    }

    float acc[4][4][4];
#pragma unroll
    for (int mi = 0; mi < 4; mi++)
#pragma unroll
        for (int ni = 0; ni < 4; ni++)
#pragma unroll
            for (int j = 0; j < 4; j++) acc[mi][ni][j] = 0.f;

    uint32_t a_l = (uint32_t)((wm * 64 + (lane & 15)) * ROW_B + (lane >> 4) * 16);
    uint32_t b_l = (uint32_t)((wn * 32 + (lane & 7) + ((lane >> 4) << 3)) * ROW_B +
                              ((lane >> 3) & 1) * 16);

    for (int st = 0; st < 32; ++st) {
        if (st + 1 < 32) { load_stage(st + 1); cp_commit(); cp_wait1(); }
        else            { cp_wait0(); }
        __syncthreads();
        uint32_t buf = sbase + (uint32_t)(st & 1) * STAGE_B;
#pragma unroll
        for (int ksub = 0; ksub < 2; ++ksub) {
            uint32_t aoff = buf + a_l + (uint32_t)ksub * 32u;
            uint32_t boff = buf + 2u * PLANE_B + b_l + (uint32_t)ksub * 32u;
            uint32_t ah[4][4], al[4][4], bh[2][4], bl[2][4];
#pragma unroll
            for (int mi = 0; mi < 4; mi++) ldm4(ah[mi], aoff + mi * (16 * ROW_B));
#pragma unroll
            for (int p = 0; p < 2; p++) {
                ldm4(bh[p], boff + p * (16 * ROW_B));
                ldm4(bl[p], boff + PLANE_B + p * (16 * ROW_B));
            }
#pragma unroll
            for (int mi = 0; mi < 4; mi++)
                ldm4(al[mi], aoff + PLANE_B + mi * (16 * ROW_B));
#pragma unroll
            for (int mi = 0; mi < 4; mi++)
#pragma unroll
                for (int ni = 0; ni < 4; ni++)
                    mma_bf16(acc[mi][ni], ah[mi], &bh[ni >> 1][(ni & 1) * 2]);
#pragma unroll
            for (int mi = 0; mi < 4; mi++)
#pragma unroll
                for (int ni = 0; ni < 4; ni++)
                    mma_bf16(acc[mi][ni], ah[mi], &bl[ni >> 1][(ni & 1) * 2]);
#pragma unroll
            for (int mi = 0; mi < 4; mi++)
#pragma unroll
                for (int ni = 0; ni < 4; ni++)
                    mma_bf16(acc[mi][ni], al[mi], &bh[ni >> 1][(ni & 1) * 2]);
        }
        __syncthreads();
    }

    // ---- epilogue: relu precompute, then per-segment weighted reduce --------
#pragma unroll
    for (int mi = 0; mi < 4; mi++)
#pragma unroll
        for (int ni = 0; ni < 4; ni++) {
            int c0 = wn * 32 + ni * 8 + tg * 2;
            float bv0 = b1s[c0], bv1 = b1s[c0 + 1];
            acc[mi][ni][0] = fmaxf(acc[mi][ni][0] + bv0, 0.f);
            acc[mi][ni][1] = fmaxf(acc[mi][ni][1] + bv1, 0.f);
            acc[mi][ni][2] = fmaxf(acc[mi][ni][2] + bv0, 0.f);
            acc[mi][ni][3] = fmaxf(acc[mi][ni][3] + bv1, 0.f);
        }
    int batch0 = bat_s[0];
    int nseg = bat_s[127] - batch0 + 1;
    for (int sg = 0; sg < nseg; ++sg) {
        int bsel = batch0 + sg;
        if (tid < 128) cols[tid] = 0.f;
        __syncthreads();
#pragma unroll
        for (int mi = 0; mi < 4; mi++) {
            int rA = wm * 64 + mi * 16 + g;
            float wA = (bat_s[rA] == bsel) ? att_s[rA] : 0.f;
            float wB = (bat_s[rA + 8] == bsel) ? att_s[rA + 8] : 0.f;
#pragma unroll
            for (int ni = 0; ni < 4; ni++) {
                int c0 = wn * 32 + ni * 8 + tg * 2;
                float v0 = acc[mi][ni][0] * wA + acc[mi][ni][2] * wB;
                float v1 = acc[mi][ni][1] * wA + acc[mi][ni][3] * wB;
#pragma unroll
                for (int o = 4; o <= 16; o <<= 1) {
                    v0 += __shfl_xor_sync(0xffffffffu, v0, o);
                    v1 += __shfl_xor_sync(0xffffffffu, v1, o);
                }
                if (g == 0) {
                    atomicAdd(&cols[c0], v0);
                    atomicAdd(&cols[c0 + 1], v1);
                }
            }
        }
        __syncthreads();
        if (tid < 128 && bsel < NB)
            atomicAdd(&ph[((size_t)(branch * NB + bsel)) * DDIM + n0 + tid], cols[tid]);
        __syncthreads();
    }
}

// ---------------- K6: layernorm + relu + last linear -----------------------
__global__ void final_kernel(const float* __restrict__ pooled,
                             const float* __restrict__ ln_g, const float* __restrict__ ln_b,
                             const float* __restrict__ W_last, const float* __restrict__ b_last,
                             float* __restrict__ out) {
    int row = blockIdx.y * NB + blockIdx.x;
    int tid = threadIdx.x;
    __shared__ float act[DDIM];
    __shared__ float red[128];

    float vals[8];
    float lsum = 0.f;
#pragma unroll
    for (int i = 0; i < 8; i++) {
        vals[i] = pooled[(size_t)row * DDIM + tid + i * 128];
        lsum += vals[i];
    }
    red[tid] = lsum;
    __syncthreads();
    for (int s = 64; s > 0; s >>= 1) {
        if (tid < s) red[tid] += red[tid + s];
        __syncthreads();
    }
    float mu = red[0] * (1.0f / DDIM);
    __syncthreads();
    float lsq = 0.f;
#pragma unroll
    for (int i = 0; i < 8; i++) {
        float d = vals[i] - mu;
        lsq += d * d;
    }
    red[tid] = lsq;
    __syncthreads();
    for (int s = 64; s > 0; s >>= 1) {
        if (tid < s) red[tid] += red[tid + s];
        __syncthreads();
    }
    float var = red[0] * (1.0f / DDIM);
    float vv = var + 1e-12f;
    float inv = rsqrtf(vv);
    inv = inv * (1.5f - 0.5f * vv * inv * inv);
    __syncthreads();
#pragma unroll
    for (int i = 0; i < 8; i++) {
        int d = tid + i * 128;
        float nvv = (vals[i] - mu) * inv * ln_g[d] + ln_b[d];
        act[d] = fmaxf(nvv, 0.f);
    }
    __syncthreads();
    if (tid < CDIM) {
        float accv = b_last[tid];
        for (int d = 0; d < DDIM; d++) accv += act[d] * W_last[(size_t)d * CDIM + tid];
        out[(size_t)row * CDIM + tid] = accv;
    }
}

// ---------------- launch ----------------------------------------------------
extern "C" void kernel_launch(void* const* d_in, const int* in_sizes, int n_in,
                              void* d_out, int out_size) {
    const float* x0 = (const float*)d_in[0];
    const float* x1 = (const float*)d_in[1];
    const float* x2 = (const float*)d_in[2];
    const int* m0 = (const int*)d_in[3];
    const int* m1 = (const int*)d_in[4];
    const int* m2 = (const int*)d_in[5];
    const float* W_attn = (const float*)d_in[6];
    const float* b_attn = (const float*)d_in[7];
    const float* W1 = (const float*)d_in[8];
    const float* b1 = (const float*)d_in[9];
    const float* W2 = (const float*)d_in[10];
    const float* b2 = (const float*)d_in[11];
    const float* ln_g = (const float*)d_in[12];
    const float* ln_b = (const float*)d_in[13];
    const float* W_last = (const float*)d_in[14];
    const float* b_last = (const float*)d_in[15];
    float* out = (float*)d_out;

    float *p_xsum, *p_nv, *p_u, *p_ub, *p_v, *p_s, *p_attn, *p_ph, *p_pooled;
    int *p_rank, *p_V, *p_off, *p_total, *p_batchof;
    __nv_bfloat16 *p_xhi, *p_xlo, *p_wth, *p_wtl;
    cudaGetSymbolAddress((void**)&p_xsum, g_xsum);
    cudaGetSymbolAddress((void**)&p_nv, g_nv);
    cudaGetSymbolAddress((void**)&p_u, g_u);
    cudaGetSymbolAddress((void**)&p_ub, g_ub);
    cudaGetSymbolAddress((void**)&p_v, g_v);
    cudaGetSymbolAddress((void**)&p_s, g_s);
    cudaGetSymbolAddress((void**)&p_attn, g_attn);
    cudaGetSymbolAddress((void**)&p_ph, g_ph);
    cudaGetSymbolAddress((void**)&p_pooled, g_pooled);
    cudaGetSymbolAddress((void**)&p_rank, g_rank);
    cudaGetSymbolAddress((void**)&p_V, g_V);
    cudaGetSymbolAddress((void**)&p_off, g_off);
    cudaGetSymbolAddress((void**)&p_total, g_total);
    cudaGetSymbolAddress((void**)&p_batchof, g_batchof);
    cudaGetSymbolAddress((void**)&p_xhi, g_xhi);
    cudaGetSymbolAddress((void**)&p_xlo, g_xlo);
    cudaGetSymbolAddress((void**)&p_wth, g_w1t_hi);
    cudaGetSymbolAddress((void**)&p_wtl, g_w1t_lo);

    cudaFuncSetAttribute(big_mma_kernel, cudaFuncAttributeMaxDynamicSharedMemorySize,
                         SMEM_REQ);

    combo_kernel<<<1408, 256>>>(W1, p_wth, p_wtl, p_ph, p_xsum, p_u, p_v,
                                p_pooled, p_ub, p_attn);
    mask_scan_kernel<<<dim3(NB, 3), 512>>>(m0, m1, m2, p_rank, p_V, p_nv);
    offsets_kernel<<<1, 96>>>(p_V, p_off, p_total, p_batchof);
    convsum_kernel<<<dim3(16, NB, 3), 256>>>(x0, x1, x2, p_rank, p_off,
                                             p_xhi, p_xlo, p_xsum, p_batchof);
    gemm96_kernel<0><<<dim3(16, 3, 8), 256>>>(p_xsum, W_attn, p_u, b_attn, p_nv, p_ub);
    gemm96_kernel<1><<<dim3(16, 3, 8), 256>>>(p_u, W_attn, p_v, nullptr, nullptr, nullptr);
    s_kernel<<<dim3(64, NB, 3), 256>>>(x0, x1, x2, p_rank, p_off, p_v, p_ub, p_s);
    softmax_kernel<<<dim3(NB, 3), 256>>>(p_s, p_off, p_V, p_attn);
    big_mma_kernel<<<dim3(8, 384), 256, SMEM_REQ>>>(p_xhi, p_xlo, p_wth, p_wtl,
                                                    b1, p_attn, p_batchof, p_total, p_ph);
    gemm96_kernel<2><<<dim3(16, 3, 8), 256>>>(p_ph, W2, p_pooled, b2, nullptr, nullptr);
    final_kernel<<<dim3(NB, 3), 128>>>(p_pooled, ln_g, ln_b, W_last, b_last, out);
}